// round 14
// baseline (speedup 1.0000x reference)
#include <cuda_runtime.h>
#include <cuda_fp16.h>
#include <math.h>
#include <stdint.h>

#define BATCH 4
#define SEQ   2048
#define DIN   1024
#define DOUT  1024
#define MTOT  (BATCH*SEQ)            // 8192
#define NCAT  (3*DOUT)               // 3072

// ---------------------------------------------------------------------------
// Scratch (device globals). A-side operands are hi/lo fp16 pairs; B-side single.
// ---------------------------------------------------------------------------
__device__ __half g_xh[(size_t)MTOT*DIN];
__device__ __half g_xl[(size_t)MTOT*DIN];
__device__ __half g_Wth[(size_t)NCAT*DIN];          // W^T concat [n][k], single
__device__ float  g_bcat[NCAT];
__device__ __half g_Qh[(size_t)MTOT*DOUT];
__device__ __half g_Ql[(size_t)MTOT*DOUT];
__device__ __half g_Kh[(size_t)MTOT*DOUT];          // single (B side of scores)
__device__ float  g_V [(size_t)MTOT*DOUT];
__device__ __half g_Vth[(size_t)BATCH*DOUT*SEQ];    // V^T [b][d][j], single
__device__ float  g_S [(size_t)BATCH*SEQ*SEQ];
__device__ __half g_Ph[(size_t)BATCH*SEQ*SEQ];
__device__ __half g_Pl[(size_t)BATCH*SEQ*SEQ];

// ---------------------------------------------------------------------------
// Baseline-PTX tensor helpers (mma.sync + ldmatrix + cp.async; plain sm_103)
// ---------------------------------------------------------------------------
__device__ __forceinline__ uint32_t smem_u32(const void* p) {
    uint32_t a;
    asm("{ .reg .u64 t; cvta.to.shared.u64 t, %1; cvt.u32.u64 %0, t; }" : "=r"(a) : "l"(p));
    return a;
}
__device__ __forceinline__ void ldsm4(uint32_t* r, uint32_t a) {
    asm volatile("ldmatrix.sync.aligned.m8n8.x4.shared.b16 {%0,%1,%2,%3}, [%4];"
        : "=r"(r[0]), "=r"(r[1]), "=r"(r[2]), "=r"(r[3]) : "r"(a));
}
__device__ __forceinline__ void mma_f16(float* c, const uint32_t* a, const uint32_t* b) {
    asm volatile("mma.sync.aligned.m16n8k16.row.col.f32.f16.f16.f32 "
        "{%0,%1,%2,%3}, {%4,%5,%6,%7}, {%8,%9}, {%0,%1,%2,%3};"
        : "+f"(c[0]), "+f"(c[1]), "+f"(c[2]), "+f"(c[3])
        : "r"(a[0]), "r"(a[1]), "r"(a[2]), "r"(a[3]), "r"(b[0]), "r"(b[1]));
}
__device__ __forceinline__ void cp16(uint32_t saddr, const void* g) {
    asm volatile("cp.async.cg.shared.global [%0], [%1], 16;" :: "r"(saddr), "l"(g));
}
#define CP_COMMIT() asm volatile("cp.async.commit_group;" ::: "memory")
#define CP_WAIT(n)  asm volatile("cp.async.wait_group %0;" :: "n"(n) : "memory")

// fp16 hi/lo split (A-side, ~22 effective mantissa bits)
__device__ __forceinline__ void split2h(float f, __half& h, __half& l) {
    h = __float2half(f);
    l = __float2half(f - __half2float(h));
}

// ---------------------------------------------------------------------------
// SMEM: per stage 3 tiles (Ah, Al, Bh), each 128 rows x 64 fp16, stride 144 B.
// Stage = 55296 B, 2-stage ring = 110592 B -> 2 CTAs/SM (221184 <= 227 KB).
// ---------------------------------------------------------------------------
#define TSTRIDE_B 144
#define TILE_B    18432
#define STAGE_B   (3*TILE_B)
#define NSTAGE    2
#define SMEM_SZ   (NSTAGE*STAGE_B)
#define NTHREADS  512

// MODE 0: QKV  (A=x split, B=Wt single, N over 3072)
// MODE 1: scores (A=Q split, B=K single, causal tiles only)
// MODE 2: PV   (A=P split, B=Vt single, K truncated)
template<int MODE>
__global__ __launch_bounds__(NTHREADS, 2) void gemm_kernel(float* __restrict__ out)
{
    extern __shared__ char smem[];
    const uint32_t sb = smem_u32(smem);
    const int t = threadIdx.x;
    const int wid = t >> 5, lane = t & 31;
    // 16 warps in a 4x4 grid; each warp owns a 32x32 subtile.
    const int m_warp = (wid & 3) * 32;
    const int n_warp = (wid >> 2) * 32;

    const __half *Ah, *Al, *Bh;
    size_t sA, sB;
    int m0, n0, nchunks, b = 0;

    if (MODE == 0) {
        m0 = blockIdx.y * 128; n0 = blockIdx.x * 128;
        Ah = g_xh + (size_t)m0 * DIN;  Al = g_xl + (size_t)m0 * DIN;
        Bh = g_Wth + (size_t)n0 * DIN;
        sA = DIN; sB = DIN; nchunks = DIN / 64;
    } else if (MODE == 1) {
        b = blockIdx.y;
        int x = blockIdx.x, it = 0;
        while ((it + 1) * (it + 2) / 2 <= x) it++;
        int jt = x - it * (it + 1) / 2;
        m0 = it * 128; n0 = jt * 128;
        Ah = g_Qh + ((size_t)b * SEQ + m0) * DOUT; Al = g_Ql + ((size_t)b * SEQ + m0) * DOUT;
        Bh = g_Kh + ((size_t)b * SEQ + n0) * DOUT;
        sA = DOUT; sB = DOUT; nchunks = DOUT / 64;
    } else {
        b = blockIdx.z;
        m0 = blockIdx.y * 128; n0 = blockIdx.x * 128;
        Ah = g_Ph + ((size_t)b * SEQ + m0) * SEQ;  Al = g_Pl + ((size_t)b * SEQ + m0) * SEQ;
        Bh = g_Vth + ((size_t)b * DOUT + n0) * SEQ;
        sA = SEQ; sB = SEQ; nchunks = (blockIdx.y + 1) * 2;   // >= 2 always
    }

    float acc[2][4][4] = {};   // [mt][nt][frag], 32 regs

    // async chunk loader: 3 tiles x 1024 x 16B = 6 cp.async per thread (512 thr)
    auto issue_chunk = [&](int buf, int kc) {
        const int k0 = kc * 64;
        #pragma unroll
        for (int l = 0; l < 6; l++) {
            int tile = l >> 1;               // 0:Ah 1:Al 2:Bh
            int e    = (l & 1) * 512 + t;    // 0..1023
            int r    = e >> 3;
            int c8   = e & 7;
            const __half* src = (tile == 0) ? Ah : (tile == 1) ? Al : Bh;
            size_t stride = (tile < 2) ? sA : sB;
            cp16(sb + buf * STAGE_B + tile * TILE_B + (uint32_t)(r * TSTRIDE_B + c8 * 16),
                 src + (size_t)r * stride + k0 + c8 * 8);
        }
        CP_COMMIT();
    };

    issue_chunk(0, 0);

    for (int c = 0; c < nchunks; c++) {
        CP_WAIT(0);                          // chunk c resident (this thread)
        __syncthreads();                     // all threads' chunk c visible;
                                             // also: buffer (c-1)&1 fully read
        if (c + 1 < nchunks)
            issue_chunk((c + 1) & 1, c + 1); // loads overlap this chunk's MMAs

        const uint32_t base = sb + (c & 1) * STAGE_B;
        const int arow = m_warp + (lane & 7) + ((lane >> 3) & 1) * 8;
        const uint32_t acol = (lane >> 4) * 16;
        // B ldsm4 over an nt-pair (16 n-rows x 16 k)
        const int brow4 = n_warp + (lane & 7) + (lane >> 4) * 8;
        const uint32_t bcol4 = ((lane >> 3) & 1) * 16;

        #pragma unroll
        for (int ks = 0; ks < 4; ks++) {
            const uint32_t kb = ks * 32;     // 16 fp16 = 32 bytes
            uint32_t bh[4][2];
            #pragma unroll
            for (int p = 0; p < 2; p++) {
                uint32_t addr = base + 2 * TILE_B + (uint32_t)(brow4 + p * 16) * TSTRIDE_B + bcol4 + kb;
                uint32_t r4[4];
                ldsm4(r4, addr);
                bh[2*p][0] = r4[0]; bh[2*p][1] = r4[1];
                bh[2*p+1][0] = r4[2]; bh[2*p+1][1] = r4[3];
            }
            #pragma unroll
            for (int mt = 0; mt < 2; mt++) {
                uint32_t addr = base + (uint32_t)(arow + mt * 16) * TSTRIDE_B + acol + kb;
                uint32_t ah[4], al[4];
                ldsm4(ah, addr);
                ldsm4(al, addr + TILE_B);
                #pragma unroll
                for (int nt = 0; nt < 4; nt++) mma_f16(acc[mt][nt], ah, bh[nt]);
                #pragma unroll
                for (int nt = 0; nt < 4; nt++) mma_f16(acc[mt][nt], al, bh[nt]);
            }
        }
        __syncthreads();                     // readers done before next issue
    }

    // ---------------- epilogue straight from registers ----------------
    const int r_loc = m_warp + (lane >> 2);          // local row (of 128), +8 pair
    const int c_loc = n_warp + (lane & 3) * 2;       // local col (of 128)

    #pragma unroll
    for (int mt = 0; mt < 2; mt++) {
        #pragma unroll
        for (int half = 0; half < 2; half++) {
            int r = m0 + r_loc + mt * 16 + half * 8;
            #pragma unroll
            for (int nt = 0; nt < 4; nt++) {
                int cc = n0 + c_loc + nt * 8;
                float v0 = acc[mt][nt][half * 2 + 0];
                float v1 = acc[mt][nt][half * 2 + 1];

                if (MODE == 0) {
                    int mat = n0 >> 10;              // tile-uniform: 0=Q 1=K 2=V
                    int nl = cc & 1023;
                    float f0 = v0 + g_bcat[cc];
                    float f1 = v1 + g_bcat[cc + 1];
                    if (mat == 2) {
                        *(float2*)&g_V[(size_t)r * DOUT + nl] = make_float2(f0, f1);
                    } else if (mat == 1) {           // K: single fp16 (B side)
                        __half2 kp; kp.x = __float2half(f0); kp.y = __float2half(f1);
                        *(__half2*)&g_Kh[(size_t)r * DOUT + nl] = kp;
                    } else {                         // Q: hi/lo split (A side)
                        __half h0, l0, h1, l1;
                        split2h(f0, h0, l0); split2h(f1, h1, l1);
                        __half2 hp; hp.x = h0; hp.y = h1;
                        __half2 lp; lp.x = l0; lp.y = l1;
                        *(__half2*)&g_Qh[(size_t)r * DOUT + nl] = hp;
                        *(__half2*)&g_Ql[(size_t)r * DOUT + nl] = lp;
                    }
                } else if (MODE == 1) {
                    const float scale = 0.03125f;    // 1/sqrt(1024)
                    float f0 = v0 * scale, f1 = v1 * scale;
                    if (m0 == n0) {                  // diagonal tile: mask j>i
                        if (cc     > r) f0 = -INFINITY;
                        if (cc + 1 > r) f1 = -INFINITY;
                    }
                    *(float2*)&g_S[((size_t)b * SEQ + r) * SEQ + cc] = make_float2(f0, f1);
                } else {
                    *(float2*)&out[((size_t)b * SEQ + r) * DOUT + cc] = make_float2(v0, v1);
                }
            }
        }
    }
}

// ---------------------------------------------------------------------------
// Prep kernels
// ---------------------------------------------------------------------------
__global__ __launch_bounds__(256) void prep_x_kernel(const float* __restrict__ x)
{
    size_t i = (size_t)blockIdx.x * 1024 + threadIdx.x * 4;
    float4 v = *(const float4*)&x[i];
    __half h, l;
    split2h(v.x, h, l); g_xh[i + 0] = h; g_xl[i + 0] = l;
    split2h(v.y, h, l); g_xh[i + 1] = h; g_xl[i + 1] = l;
    split2h(v.z, h, l); g_xh[i + 2] = h; g_xl[i + 2] = l;
    split2h(v.w, h, l); g_xh[i + 3] = h; g_xl[i + 3] = l;
}

__global__ void prep_bias_kernel(const float* __restrict__ bq,
                                 const float* __restrict__ bk,
                                 const float* __restrict__ bv)
{
    int i = blockIdx.x * 256 + threadIdx.x;   // 0..3071
    g_bcat[i] = (i < 1024) ? bq[i] : (i < 2048) ? bk[i - 1024] : bv[i - 2048];
}

// W [k][n] -> Wt [z*1024 + n][k], single fp16 (B side)
__global__ void prep_wt_kernel(const float* __restrict__ Wq,
                               const float* __restrict__ Wk,
                               const float* __restrict__ Wv)
{
    __shared__ float tl[32][33];
    const int z = blockIdx.z;
    const float* W = (z == 0) ? Wq : (z == 1) ? Wk : Wv;
    int kk = blockIdx.y * 32, nn = blockIdx.x * 32;
    int tx = threadIdx.x, ty = threadIdx.y;
    #pragma unroll
    for (int i = 0; i < 4; i++)
        tl[ty + i * 8][tx] = W[(size_t)(kk + ty + i * 8) * DOUT + nn + tx];
    __syncthreads();
    #pragma unroll
    for (int i = 0; i < 4; i++) {
        float f = tl[tx][ty + i * 8];        // = W[kk+tx][nn+ty+i*8]
        size_t row = (size_t)z * 1024 + nn + ty + i * 8;
        g_Wth[row * DIN + kk + tx] = __float2half(f);
    }
}

// V [b][j][d] -> Vt [b][d][j], single fp16 (B side)
__global__ void vtrans_kernel()
{
    __shared__ float tl[32][33];
    const int bz = blockIdx.z;
    int jj = blockIdx.x * 32, dd = blockIdx.y * 32;
    int tx = threadIdx.x, ty = threadIdx.y;
    #pragma unroll
    for (int i = 0; i < 4; i++)
        tl[ty + i * 8][tx] = g_V[((size_t)bz * SEQ + jj + ty + i * 8) * DOUT + dd + tx];
    __syncthreads();
    #pragma unroll
    for (int i = 0; i < 4; i++) {
        float f = tl[tx][ty + i * 8];        // = V[jj+tx][dd+ty+i*8]
        size_t row = (size_t)bz * DOUT + dd + ty + i * 8;
        g_Vth[row * SEQ + jj + tx] = __float2half(f);
    }
}

// ---------------------------------------------------------------------------
// Softmax + P split; writes only the causally live region (j < row_end)
// ---------------------------------------------------------------------------
__device__ __forceinline__ float wr_max(float v) {
    #pragma unroll
    for (int o = 16; o > 0; o >>= 1) v = fmaxf(v, __shfl_xor_sync(0xFFFFFFFFu, v, o));
    return v;
}
__device__ __forceinline__ float wr_sum(float v) {
    #pragma unroll
    for (int o = 16; o > 0; o >>= 1) v += __shfl_xor_sync(0xFFFFFFFFu, v, o);
    return v;
}

__global__ __launch_bounds__(256) void softmax_split_kernel()
{
    const size_t row = blockIdx.x;          // b*SEQ + i
    const int i_in_b = (int)(row & (SEQ - 1));
    const int row_end = ((i_in_b >> 7) + 1) << 7;   // written (tile) region
    const float* Srow = g_S + row * SEQ;
    const int t = threadIdx.x;
    __shared__ float red[8];

    float vals[8];
    float mx = -INFINITY;
    #pragma unroll
    for (int l = 0; l < 8; l++) {
        int j = t + l * 256;
        vals[l] = (j < row_end) ? Srow[j] : -INFINITY;
        mx = fmaxf(mx, vals[l]);
    }
    mx = wr_max(mx);
    if ((t & 31) == 0) red[t >> 5] = mx;
    __syncthreads();
    if (t < 8) {
        float v = red[t];
        #pragma unroll
        for (int o = 4; o > 0; o >>= 1) v = fmaxf(v, __shfl_xor_sync(0xFFu, v, o));
        red[t] = v;
    }
    __syncthreads();
    mx = red[0];

    float sum = 0.f;
    #pragma unroll
    for (int l = 0; l < 8; l++) {
        float e = (vals[l] == -INFINITY) ? 0.f : __expf(vals[l] - mx);
        vals[l] = e;
        sum += e;
    }
    sum = wr_sum(sum);
    __syncthreads();
    if ((t & 31) == 0) red[t >> 5] = sum;
    __syncthreads();
    if (t < 8) {
        float v = red[t];
        #pragma unroll
        for (int o = 4; o > 0; o >>= 1) v += __shfl_xor_sync(0xFFu, v, o);
        red[t] = v;
    }
    __syncthreads();
    const float inv = 1.f / red[0];

    #pragma unroll
    for (int l = 0; l < 8; l++) {
        int j = t + l * 256;
        if (j < row_end) {
            float p = vals[l] * inv;
            __half h, lo; split2h(p, h, lo);
            g_Ph[row * SEQ + j] = h;
            g_Pl[row * SEQ + j] = lo;
        }
    }
}

// ---------------------------------------------------------------------------
extern "C" void kernel_launch(void* const* d_in, const int* in_sizes, int n_in,
                              void* d_out, int out_size)
{
    const float* x  = (const float*)d_in[0];
    const float* Wq = (const float*)d_in[1];
    const float* bq = (const float*)d_in[2];
    const float* Wk = (const float*)d_in[3];
    const float* bk = (const float*)d_in[4];
    const float* Wv = (const float*)d_in[5];
    const float* bv = (const float*)d_in[6];
    float* out = (float*)d_out;

    cudaFuncSetAttribute(gemm_kernel<0>, cudaFuncAttributeMaxDynamicSharedMemorySize, SMEM_SZ);
    cudaFuncSetAttribute(gemm_kernel<1>, cudaFuncAttributeMaxDynamicSharedMemorySize, SMEM_SZ);
    cudaFuncSetAttribute(gemm_kernel<2>, cudaFuncAttributeMaxDynamicSharedMemorySize, SMEM_SZ);

    prep_x_kernel<<<MTOT * DIN / 1024, 256>>>(x);
    prep_bias_kernel<<<NCAT / 256, 256>>>(bq, bk, bv);
    prep_wt_kernel<<<dim3(DOUT / 32, DIN / 32, 3), dim3(32, 8)>>>(Wq, Wk, Wv);

    // QKV: N = 3072 concat, M = 8192
    gemm_kernel<0><<<dim3(NCAT / 128, MTOT / 128), NTHREADS, SMEM_SZ>>>(out);

    vtrans_kernel<<<dim3(SEQ / 32, DOUT / 32, BATCH), dim3(32, 8)>>>();

    // Scores: lower-triangular tiles only (16*17/2 = 136 per batch)
    gemm_kernel<1><<<dim3(136, BATCH), NTHREADS, SMEM_SZ>>>(out);

    softmax_split_kernel<<<BATCH * SEQ, 256>>>();

    // PV: K truncated by causality inside kernel
    gemm_kernel<2><<<dim3(DOUT / 128, SEQ / 128, BATCH), NTHREADS, SMEM_SZ>>>(out);
}

// round 15
// speedup vs baseline: 1.4826x; 1.4826x over previous
#include <cuda_runtime.h>
#include <cuda_fp16.h>
#include <math.h>
#include <stdint.h>

#define BATCH 4
#define SEQ   2048
#define DIN   1024
#define DOUT  1024
#define MTOT  (BATCH*SEQ)            // 8192
#define NCAT  (3*DOUT)               // 3072

// ---------------------------------------------------------------------------
// Scratch (device globals). A-side operands are hi/lo fp16 pairs; B-side single.
// ---------------------------------------------------------------------------
__device__ __half g_xh[(size_t)MTOT*DIN];
__device__ __half g_xl[(size_t)MTOT*DIN];
__device__ __half g_Wth[(size_t)NCAT*DIN];          // W^T concat [n][k], single
__device__ float  g_bcat[NCAT];
__device__ __half g_Qh[(size_t)MTOT*DOUT];
__device__ __half g_Ql[(size_t)MTOT*DOUT];
__device__ __half g_Kh[(size_t)MTOT*DOUT];          // single (B side of scores)
__device__ float  g_V [(size_t)MTOT*DOUT];
__device__ __half g_Vth[(size_t)BATCH*DOUT*SEQ];    // V^T [b][d][j], single
__device__ float  g_S [(size_t)BATCH*SEQ*SEQ];
__device__ __half g_Ph[(size_t)BATCH*SEQ*SEQ];
__device__ __half g_Pl[(size_t)BATCH*SEQ*SEQ];

// ---------------------------------------------------------------------------
// Baseline-PTX tensor helpers (mma.sync + ldmatrix + cp.async; plain sm_103)
// ---------------------------------------------------------------------------
__device__ __forceinline__ uint32_t smem_u32(const void* p) {
    uint32_t a;
    asm("{ .reg .u64 t; cvta.to.shared.u64 t, %1; cvt.u32.u64 %0, t; }" : "=r"(a) : "l"(p));
    return a;
}
__device__ __forceinline__ void ldsm4(uint32_t* r, uint32_t a) {
    asm volatile("ldmatrix.sync.aligned.m8n8.x4.shared.b16 {%0,%1,%2,%3}, [%4];"
        : "=r"(r[0]), "=r"(r[1]), "=r"(r[2]), "=r"(r[3]) : "r"(a));
}
__device__ __forceinline__ void mma_f16(float* c, const uint32_t* a, const uint32_t* b) {
    asm volatile("mma.sync.aligned.m16n8k16.row.col.f32.f16.f16.f32 "
        "{%0,%1,%2,%3}, {%4,%5,%6,%7}, {%8,%9}, {%0,%1,%2,%3};"
        : "+f"(c[0]), "+f"(c[1]), "+f"(c[2]), "+f"(c[3])
        : "r"(a[0]), "r"(a[1]), "r"(a[2]), "r"(a[3]), "r"(b[0]), "r"(b[1]));
}
__device__ __forceinline__ void cp16(uint32_t saddr, const void* g) {
    asm volatile("cp.async.cg.shared.global [%0], [%1], 16;" :: "r"(saddr), "l"(g));
}
#define CP_COMMIT() asm volatile("cp.async.commit_group;" ::: "memory")
#define CP_WAIT(n)  asm volatile("cp.async.wait_group %0;" :: "n"(n) : "memory")

// fp16 hi/lo split (A-side, ~22 effective mantissa bits)
__device__ __forceinline__ void split2h(float f, __half& h, __half& l) {
    h = __float2half(f);
    l = __float2half(f - __half2float(h));
}

// ---------------------------------------------------------------------------
// CTA tile: 128 (M) x 256 (N), K-chunk 64.
// SMEM per stage: Ah(128x64) + Al(128x64) + Bh(256x64), fp16, row stride 144 B.
// A tile 18432 B, B tile 36864 B -> stage 73728 B; 3-stage ring = 221184 B.
// ---------------------------------------------------------------------------
#define TSTRIDE_B 144
#define ATILE_B   18432
#define STAGE_B   73728
#define NSTAGE    3
#define SMEM_SZ   (NSTAGE*STAGE_B)
#define NTHREADS  512

// MODE 0: QKV  (A=x split, B=Wt single, N over 3072)
// MODE 1: scores (A=Q split, B=K single, causal tiles only)
// MODE 2: PV   (A=P split, B=Vt single, K truncated)
template<int MODE>
__global__ __launch_bounds__(NTHREADS) void gemm_kernel(float* __restrict__ out)
{
    extern __shared__ char smem[];
    const uint32_t sb = smem_u32(smem);
    const int t = threadIdx.x;
    const int wid = t >> 5, lane = t & 31;
    // 16 warps: 4 m-groups x 4 n-groups; each warp owns a 32x64 subtile.
    const int m_warp = (wid & 3) * 32;
    const int n_warp = (wid >> 2) * 64;

    const __half *Ah, *Al, *Bh;
    size_t sA, sB;
    int m0, n0, nchunks, b = 0;

    if (MODE == 0) {
        m0 = blockIdx.y * 128; n0 = blockIdx.x * 256;
        Ah = g_xh + (size_t)m0 * DIN;  Al = g_xl + (size_t)m0 * DIN;
        Bh = g_Wth + (size_t)n0 * DIN;
        sA = DIN; sB = DIN; nchunks = DIN / 64;
    } else if (MODE == 1) {
        b = blockIdx.y;
        // causal tiles, 128x256: row it has (it>>1)+1 tiles; 72 per batch
        int x = blockIdx.x, it = 0, acc0 = 0;
        while (acc0 + (it / 2 + 1) <= x) { acc0 += it / 2 + 1; it++; }
        int jt = x - acc0;
        m0 = it * 128; n0 = jt * 256;
        Ah = g_Qh + ((size_t)b * SEQ + m0) * DOUT; Al = g_Ql + ((size_t)b * SEQ + m0) * DOUT;
        Bh = g_Kh + ((size_t)b * SEQ + n0) * DOUT;
        sA = DOUT; sB = DOUT; nchunks = DOUT / 64;
    } else {
        b = blockIdx.z;
        m0 = blockIdx.y * 128; n0 = blockIdx.x * 256;
        Ah = g_Ph + ((size_t)b * SEQ + m0) * SEQ;  Al = g_Pl + ((size_t)b * SEQ + m0) * SEQ;
        Bh = g_Vth + ((size_t)b * DOUT + n0) * SEQ;
        sA = SEQ; sB = SEQ; nchunks = (blockIdx.y + 1) * 2;   // >= 2 always
    }

    float acc[2][8][4] = {};   // [mt][nt][frag], 64 regs

    // async chunk loader: A 2x(128x8) + B (256x8) 16B-chunks = 8 cp16/thread
    auto issue_chunk = [&](int buf, int kc) {
        const int k0 = kc * 64;
        const uint32_t sbase = sb + buf * STAGE_B;
        #pragma unroll
        for (int l = 0; l < 4; l++) {        // A tiles: Ah, Al
            int tile = l >> 1;               // 0:Ah 1:Al
            int e    = (l & 1) * 512 + t;    // 0..1023
            int r    = e >> 3;
            int c8   = e & 7;
            const __half* src = (tile == 0) ? Ah : Al;
            cp16(sbase + tile * ATILE_B + (uint32_t)(r * TSTRIDE_B + c8 * 16),
                 src + (size_t)r * sA + k0 + c8 * 8);
        }
        #pragma unroll
        for (int l = 0; l < 4; l++) {        // B tile: 256 rows
            int e  = l * 512 + t;            // 0..2047
            int r  = e >> 3;
            int c8 = e & 7;
            cp16(sbase + 2 * ATILE_B + (uint32_t)(r * TSTRIDE_B + c8 * 16),
                 Bh + (size_t)r * sB + k0 + c8 * 8);
        }
        CP_COMMIT();
    };

    // prologue: prefetch up to NSTAGE-1 = 2 chunks
    const int npro = (nchunks < NSTAGE - 1) ? nchunks : (NSTAGE - 1);
    for (int kc = 0; kc < npro; kc++) issue_chunk(kc, kc);

    for (int c = 0; c < nchunks; c++) {
        if (c + 1 < nchunks) { CP_WAIT(1); } else { CP_WAIT(0); }
        __syncthreads();                     // chunk c resident; stage (c-1)%3 free
        if (c + NSTAGE - 1 < nchunks)
            issue_chunk((c + NSTAGE - 1) % NSTAGE, c + NSTAGE - 1);

        const uint32_t base = sb + (c % NSTAGE) * STAGE_B;
        const int arow = m_warp + (lane & 7) + ((lane >> 3) & 1) * 8;
        const uint32_t acol = (lane >> 4) * 16;
        // B ldsm4 over an nt-pair (16 n-rows x 16 k)
        const int brow4 = n_warp + (lane & 7) + (lane >> 4) * 8;
        const uint32_t bcol4 = ((lane >> 3) & 1) * 16;

        #pragma unroll
        for (int ks = 0; ks < 4; ks++) {
            const uint32_t kb = ks * 32;     // 16 fp16 = 32 bytes
            uint32_t bh[8][2];
            #pragma unroll
            for (int q = 0; q < 4; q++) {
                uint32_t addr = base + 2 * ATILE_B + (uint32_t)(brow4 + q * 16) * TSTRIDE_B + bcol4 + kb;
                uint32_t r4[4];
                ldsm4(r4, addr);
                bh[2*q][0] = r4[0]; bh[2*q][1] = r4[1];
                bh[2*q+1][0] = r4[2]; bh[2*q+1][1] = r4[3];
            }
            #pragma unroll
            for (int mt = 0; mt < 2; mt++) {
                uint32_t addr = base + (uint32_t)(arow + mt * 16) * TSTRIDE_B + acol + kb;
                uint32_t ah[4], al[4];
                ldsm4(ah, addr);
                ldsm4(al, addr + ATILE_B);
                #pragma unroll
                for (int nt = 0; nt < 8; nt++) mma_f16(acc[mt][nt], ah, bh[nt]);
                #pragma unroll
                for (int nt = 0; nt < 8; nt++) mma_f16(acc[mt][nt], al, bh[nt]);
            }
        }
    }

    // ---------------- epilogue straight from registers ----------------
    const int r_loc = m_warp + (lane >> 2);          // local row (of 128), +8 pair
    const int c_loc = n_warp + (lane & 3) * 2;       // local col (of 256)

    #pragma unroll
    for (int mt = 0; mt < 2; mt++) {
        #pragma unroll
        for (int half = 0; half < 2; half++) {
            int r = m0 + r_loc + mt * 16 + half * 8;
            #pragma unroll
            for (int nt = 0; nt < 8; nt++) {
                int cc = n0 + c_loc + nt * 8;
                float v0 = acc[mt][nt][half * 2 + 0];
                float v1 = acc[mt][nt][half * 2 + 1];

                if (MODE == 0) {
                    int mat = n0 >> 10;              // tile-uniform (256 | 1024)
                    int nl = cc & 1023;
                    float f0 = v0 + g_bcat[cc];
                    float f1 = v1 + g_bcat[cc + 1];
                    if (mat == 2) {
                        *(float2*)&g_V[(size_t)r * DOUT + nl] = make_float2(f0, f1);
                    } else if (mat == 1) {           // K: single fp16 (B side)
                        __half2 kp; kp.x = __float2half(f0); kp.y = __float2half(f1);
                        *(__half2*)&g_Kh[(size_t)r * DOUT + nl] = kp;
                    } else {                         // Q: hi/lo split (A side)
                        __half h0, l0, h1, l1;
                        split2h(f0, h0, l0); split2h(f1, h1, l1);
                        __half2 hp; hp.x = h0; hp.y = h1;
                        __half2 lp; lp.x = l0; lp.y = l1;
                        *(__half2*)&g_Qh[(size_t)r * DOUT + nl] = hp;
                        *(__half2*)&g_Ql[(size_t)r * DOUT + nl] = lp;
                    }
                } else if (MODE == 1) {
                    const float scale = 0.03125f;    // 1/sqrt(1024)
                    float f0 = v0 * scale, f1 = v1 * scale;
                    if (n0 + 255 > m0) {             // diagonal crosses tile
                        if (cc     > r) f0 = -INFINITY;
                        if (cc + 1 > r) f1 = -INFINITY;
                    }
                    *(float2*)&g_S[((size_t)b * SEQ + r) * SEQ + cc] = make_float2(f0, f1);
                } else {
                    *(float2*)&out[((size_t)b * SEQ + r) * DOUT + cc] = make_float2(v0, v1);
                }
            }
        }
    }
}

// ---------------------------------------------------------------------------
// Prep kernels
// ---------------------------------------------------------------------------
__global__ __launch_bounds__(256) void prep_x_kernel(const float* __restrict__ x)
{
    size_t i = (size_t)blockIdx.x * 1024 + threadIdx.x * 4;
    float4 v = *(const float4*)&x[i];
    __half h, l;
    split2h(v.x, h, l); g_xh[i + 0] = h; g_xl[i + 0] = l;
    split2h(v.y, h, l); g_xh[i + 1] = h; g_xl[i + 1] = l;
    split2h(v.z, h, l); g_xh[i + 2] = h; g_xl[i + 2] = l;
    split2h(v.w, h, l); g_xh[i + 3] = h; g_xl[i + 3] = l;
}

__global__ void prep_bias_kernel(const float* __restrict__ bq,
                                 const float* __restrict__ bk,
                                 const float* __restrict__ bv)
{
    int i = blockIdx.x * 256 + threadIdx.x;   // 0..3071
    g_bcat[i] = (i < 1024) ? bq[i] : (i < 2048) ? bk[i - 1024] : bv[i - 2048];
}

// W [k][n] -> Wt [z*1024 + n][k], single fp16 (B side)
__global__ void prep_wt_kernel(const float* __restrict__ Wq,
                               const float* __restrict__ Wk,
                               const float* __restrict__ Wv)
{
    __shared__ float tl[32][33];
    const int z = blockIdx.z;
    const float* W = (z == 0) ? Wq : (z == 1) ? Wk : Wv;
    int kk = blockIdx.y * 32, nn = blockIdx.x * 32;
    int tx = threadIdx.x, ty = threadIdx.y;
    #pragma unroll
    for (int i = 0; i < 4; i++)
        tl[ty + i * 8][tx] = W[(size_t)(kk + ty + i * 8) * DOUT + nn + tx];
    __syncthreads();
    #pragma unroll
    for (int i = 0; i < 4; i++) {
        float f = tl[tx][ty + i * 8];        // = W[kk+tx][nn+ty+i*8]
        size_t row = (size_t)z * 1024 + nn + ty + i * 8;
        g_Wth[row * DIN + kk + tx] = __float2half(f);
    }
}

// V [b][j][d] -> Vt [b][d][j], single fp16 (B side)
__global__ void vtrans_kernel()
{
    __shared__ float tl[32][33];
    const int bz = blockIdx.z;
    int jj = blockIdx.x * 32, dd = blockIdx.y * 32;
    int tx = threadIdx.x, ty = threadIdx.y;
    #pragma unroll
    for (int i = 0; i < 4; i++)
        tl[ty + i * 8][tx] = g_V[((size_t)bz * SEQ + jj + ty + i * 8) * DOUT + dd + tx];
    __syncthreads();
    #pragma unroll
    for (int i = 0; i < 4; i++) {
        float f = tl[tx][ty + i * 8];        // = V[jj+tx][dd+ty+i*8]
        size_t row = (size_t)bz * DOUT + dd + ty + i * 8;
        g_Vth[row * SEQ + jj + tx] = __float2half(f);
    }
}

// ---------------------------------------------------------------------------
// Softmax + P split; writes only the causally live region (j < row_end)
// ---------------------------------------------------------------------------
__device__ __forceinline__ float wr_max(float v) {
    #pragma unroll
    for (int o = 16; o > 0; o >>= 1) v = fmaxf(v, __shfl_xor_sync(0xFFFFFFFFu, v, o));
    return v;
}
__device__ __forceinline__ float wr_sum(float v) {
    #pragma unroll
    for (int o = 16; o > 0; o >>= 1) v += __shfl_xor_sync(0xFFFFFFFFu, v, o);
    return v;
}

__global__ __launch_bounds__(256) void softmax_split_kernel()
{
    const size_t row = blockIdx.x;          // b*SEQ + i
    const int i_in_b = (int)(row & (SEQ - 1));
    const int row_end = ((i_in_b >> 7) + 1) << 7;   // P region consumed by PV
    const float* Srow = g_S + row * SEQ;
    const int t = threadIdx.x;
    __shared__ float red[8];

    float vals[8];
    float mx = -INFINITY;
    #pragma unroll
    for (int l = 0; l < 8; l++) {
        int j = t + l * 256;
        vals[l] = (j < row_end) ? Srow[j] : -INFINITY;
        mx = fmaxf(mx, vals[l]);
    }
    mx = wr_max(mx);
    if ((t & 31) == 0) red[t >> 5] = mx;
    __syncthreads();
    if (t < 8) {
        float v = red[t];
        #pragma unroll
        for (int o = 4; o > 0; o >>= 1) v = fmaxf(v, __shfl_xor_sync(0xFFu, v, o));
        red[t] = v;
    }
    __syncthreads();
    mx = red[0];

    float sum = 0.f;
    #pragma unroll
    for (int l = 0; l < 8; l++) {
        float e = (vals[l] == -INFINITY) ? 0.f : __expf(vals[l] - mx);
        vals[l] = e;
        sum += e;
    }
    sum = wr_sum(sum);
    __syncthreads();
    if ((t & 31) == 0) red[t >> 5] = sum;
    __syncthreads();
    if (t < 8) {
        float v = red[t];
        #pragma unroll
        for (int o = 4; o > 0; o >>= 1) v += __shfl_xor_sync(0xFFu, v, o);
        red[t] = v;
    }
    __syncthreads();
    const float inv = 1.f / red[0];

    #pragma unroll
    for (int l = 0; l < 8; l++) {
        int j = t + l * 256;
        if (j < row_end) {
            float p = vals[l] * inv;
            __half h, lo; split2h(p, h, lo);
            g_Ph[row * SEQ + j] = h;
            g_Pl[row * SEQ + j] = lo;
        }
    }
}

// ---------------------------------------------------------------------------
extern "C" void kernel_launch(void* const* d_in, const int* in_sizes, int n_in,
                              void* d_out, int out_size)
{
    const float* x  = (const float*)d_in[0];
    const float* Wq = (const float*)d_in[1];
    const float* bq = (const float*)d_in[2];
    const float* Wk = (const float*)d_in[3];
    const float* bk = (const float*)d_in[4];
    const float* Wv = (const float*)d_in[5];
    const float* bv = (const float*)d_in[6];
    float* out = (float*)d_out;

    cudaFuncSetAttribute(gemm_kernel<0>, cudaFuncAttributeMaxDynamicSharedMemorySize, SMEM_SZ);
    cudaFuncSetAttribute(gemm_kernel<1>, cudaFuncAttributeMaxDynamicSharedMemorySize, SMEM_SZ);
    cudaFuncSetAttribute(gemm_kernel<2>, cudaFuncAttributeMaxDynamicSharedMemorySize, SMEM_SZ);

    prep_x_kernel<<<MTOT * DIN / 1024, 256>>>(x);
    prep_bias_kernel<<<NCAT / 256, 256>>>(bq, bk, bv);
    prep_wt_kernel<<<dim3(DOUT / 32, DIN / 32, 3), dim3(32, 8)>>>(Wq, Wk, Wv);

    // QKV: N = 3072 concat (12 tiles of 256), M = 8192 (64 tiles of 128)
    gemm_kernel<0><<<dim3(NCAT / 256, MTOT / 128), NTHREADS, SMEM_SZ>>>(out);

    vtrans_kernel<<<dim3(SEQ / 32, DOUT / 32, BATCH), dim3(32, 8)>>>();

    // Scores: 128x256 causal tiles; 72 per batch
    gemm_kernel<1><<<dim3(72, BATCH), NTHREADS, SMEM_SZ>>>(out);

    softmax_split_kernel<<<BATCH * SEQ, 256>>>();

    // PV: K truncated by causality inside kernel; N = 1024 (4 tiles of 256)
    gemm_kernel<2><<<dim3(DOUT / 256, SEQ / 128, BATCH), NTHREADS, SMEM_SZ>>>(out);
}

// round 16
// speedup vs baseline: 1.7597x; 1.1869x over previous
#include <cuda_runtime.h>
#include <cuda_fp16.h>
#include <math.h>
#include <stdint.h>

#define BATCH 4
#define SEQ   2048
#define DIN   1024
#define DOUT  1024
#define MTOT  (BATCH*SEQ)            // 8192
#define NCAT  (3*DOUT)               // 3072

// ---------------------------------------------------------------------------
// Scratch. QKV A-side (x) is hi/lo fp16; everything downstream single fp16.
// ---------------------------------------------------------------------------
__device__ __half g_xh[(size_t)MTOT*DIN];
__device__ __half g_xl[(size_t)MTOT*DIN];
__device__ __half g_Wth[(size_t)NCAT*DIN];          // W^T concat [n][k]
__device__ float  g_bcat[NCAT];
__device__ __half g_Qh[(size_t)MTOT*DOUT];          // single fp16
__device__ __half g_Kh[(size_t)MTOT*DOUT];          // single fp16
__device__ float  g_V [(size_t)MTOT*DOUT];
__device__ __half g_Vth[(size_t)BATCH*DOUT*SEQ];    // V^T [b][d][j]
__device__ float  g_S [(size_t)BATCH*SEQ*SEQ];
__device__ __half g_Ph[(size_t)BATCH*SEQ*SEQ];      // single fp16

// ---------------------------------------------------------------------------
// Baseline-PTX tensor helpers (mma.sync + ldmatrix + cp.async; plain sm_103)
// ---------------------------------------------------------------------------
__device__ __forceinline__ uint32_t smem_u32(const void* p) {
    uint32_t a;
    asm("{ .reg .u64 t; cvta.to.shared.u64 t, %1; cvt.u32.u64 %0, t; }" : "=r"(a) : "l"(p));
    return a;
}
__device__ __forceinline__ void ldsm4(uint32_t* r, uint32_t a) {
    asm volatile("ldmatrix.sync.aligned.m8n8.x4.shared.b16 {%0,%1,%2,%3}, [%4];"
        : "=r"(r[0]), "=r"(r[1]), "=r"(r[2]), "=r"(r[3]) : "r"(a));
}
__device__ __forceinline__ void mma_f16(float* c, const uint32_t* a, const uint32_t* b) {
    asm volatile("mma.sync.aligned.m16n8k16.row.col.f32.f16.f16.f32 "
        "{%0,%1,%2,%3}, {%4,%5,%6,%7}, {%8,%9}, {%0,%1,%2,%3};"
        : "+f"(c[0]), "+f"(c[1]), "+f"(c[2]), "+f"(c[3])
        : "r"(a[0]), "r"(a[1]), "r"(a[2]), "r"(a[3]), "r"(b[0]), "r"(b[1]));
}
__device__ __forceinline__ void cp16(uint32_t saddr, const void* g) {
    asm volatile("cp.async.cg.shared.global [%0], [%1], 16;" :: "r"(saddr), "l"(g));
}
#define CP_COMMIT() asm volatile("cp.async.commit_group;" ::: "memory")
#define CP_WAIT(n)  asm volatile("cp.async.wait_group %0;" :: "n"(n) : "memory")

// fp16 hi/lo split (~22 effective mantissa bits)
__device__ __forceinline__ void split2h(float f, __half& h, __half& l) {
    h = __float2half(f);
    l = __float2half(f - __half2float(h));
}

// ---------------------------------------------------------------------------
// CTA tile: 128 (M) x 256 (N), K-chunk 64, row stride 144 B.
// MODE 0 stage: Ah+Al+Bh = 18432*2+36864 = 73728 B; MODE 1/2: Ah+Bh = 55296 B.
// 3-stage ring either way (221184 / 165888 B).
// ---------------------------------------------------------------------------
#define TSTRIDE_B 144
#define ATILE_B   18432
#define BTILE_B   36864
#define NSTAGE    3
#define NTHREADS  512

// MODE 0: QKV  (A=x hi/lo, B=Wt, 2 products)
// MODE 1: scores (A=Q, B=K, 1 product, causal tiles only)
// MODE 2: PV   (A=P, B=Vt, 1 product, K truncated)
template<int MODE>
__global__ __launch_bounds__(NTHREADS) void gemm_kernel(float* __restrict__ out)
{
    constexpr int NPROD = (MODE == 0) ? 2 : 1;
    constexpr uint32_t BOFF    = NPROD * ATILE_B;
    constexpr uint32_t STAGE_B = BOFF + BTILE_B;

    extern __shared__ char smem[];
    const uint32_t sb = smem_u32(smem);
    const int t = threadIdx.x;
    const int wid = t >> 5, lane = t & 31;
    // 16 warps: 4 m-groups x 4 n-groups; each warp owns a 32x64 subtile.
    const int m_warp = (wid & 3) * 32;
    const int n_warp = (wid >> 2) * 64;

    const __half *Ah, *Al = nullptr, *Bh;
    size_t sA, sB;
    int m0, n0, nchunks, b = 0;

    if (MODE == 0) {
        m0 = blockIdx.y * 128; n0 = blockIdx.x * 256;
        Ah = g_xh + (size_t)m0 * DIN;  Al = g_xl + (size_t)m0 * DIN;
        Bh = g_Wth + (size_t)n0 * DIN;
        sA = DIN; sB = DIN; nchunks = DIN / 64;
    } else if (MODE == 1) {
        b = blockIdx.y;
        // causal tiles, 128x256: row it has (it/2)+1 tiles; 72 per batch
        int x = blockIdx.x, it = 0, acc0 = 0;
        while (acc0 + (it / 2 + 1) <= x) { acc0 += it / 2 + 1; it++; }
        int jt = x - acc0;
        m0 = it * 128; n0 = jt * 256;
        Ah = g_Qh + ((size_t)b * SEQ + m0) * DOUT;
        Bh = g_Kh + ((size_t)b * SEQ + n0) * DOUT;
        sA = DOUT; sB = DOUT; nchunks = DOUT / 64;
    } else {
        b = blockIdx.z;
        m0 = blockIdx.y * 128; n0 = blockIdx.x * 256;
        Ah = g_Ph + ((size_t)b * SEQ + m0) * SEQ;
        Bh = g_Vth + ((size_t)b * DOUT + n0) * SEQ;
        sA = SEQ; sB = SEQ; nchunks = (blockIdx.y + 1) * 2;   // >= 2 always
    }

    float acc[2][8][4] = {};   // [mt][nt][frag], 64 regs

    // async chunk loader (512 threads)
    auto issue_chunk = [&](int buf, int kc) {
        const int k0 = kc * 64;
        const uint32_t sbase = sb + buf * STAGE_B;
        #pragma unroll
        for (int l = 0; l < 2 * NPROD; l++) {    // A tiles (128 rows each)
            int tile = l >> 1;                   // 0:Ah (1:Al)
            int e    = (l & 1) * 512 + t;        // 0..1023
            int r    = e >> 3;
            int c8   = e & 7;
            const __half* src = (tile == 0) ? Ah : Al;
            cp16(sbase + tile * ATILE_B + (uint32_t)(r * TSTRIDE_B + c8 * 16),
                 src + (size_t)r * sA + k0 + c8 * 8);
        }
        #pragma unroll
        for (int l = 0; l < 4; l++) {            // B tile: 256 rows
            int e  = l * 512 + t;                // 0..2047
            int r  = e >> 3;
            int c8 = e & 7;
            cp16(sbase + BOFF + (uint32_t)(r * TSTRIDE_B + c8 * 16),
                 Bh + (size_t)r * sB + k0 + c8 * 8);
        }
        CP_COMMIT();
    };

    // prologue: prefetch up to NSTAGE-1 = 2 chunks
    const int npro = (nchunks < NSTAGE - 1) ? nchunks : (NSTAGE - 1);
    for (int kc = 0; kc < npro; kc++) issue_chunk(kc, kc);

    for (int c = 0; c < nchunks; c++) {
        if (c + 1 < nchunks) { CP_WAIT(1); } else { CP_WAIT(0); }
        __syncthreads();                     // chunk c resident; stage (c-1)%3 free
        if (c + NSTAGE - 1 < nchunks)
            issue_chunk((c + NSTAGE - 1) % NSTAGE, c + NSTAGE - 1);

        const uint32_t base = sb + (c % NSTAGE) * STAGE_B;
        const int arow = m_warp + (lane & 7) + ((lane >> 3) & 1) * 8;
        const uint32_t acol = (lane >> 4) * 16;
        // B ldsm4 over an nt-pair (16 n-rows x 16 k)
        const int brow4 = n_warp + (lane & 7) + (lane >> 4) * 8;
        const uint32_t bcol4 = ((lane >> 3) & 1) * 16;

        #pragma unroll
        for (int ks = 0; ks < 4; ks++) {
            const uint32_t kb = ks * 32;     // 16 fp16 = 32 bytes
            uint32_t bh[8][2];
            #pragma unroll
            for (int q = 0; q < 4; q++) {
                uint32_t addr = base + BOFF + (uint32_t)(brow4 + q * 16) * TSTRIDE_B + bcol4 + kb;
                uint32_t r4[4];
                ldsm4(r4, addr);
                bh[2*q][0] = r4[0]; bh[2*q][1] = r4[1];
                bh[2*q+1][0] = r4[2]; bh[2*q+1][1] = r4[3];
            }
            #pragma unroll
            for (int mt = 0; mt < 2; mt++) {
                uint32_t addr = base + (uint32_t)(arow + mt * 16) * TSTRIDE_B + acol + kb;
                uint32_t ah[4];
                ldsm4(ah, addr);
                #pragma unroll
                for (int nt = 0; nt < 8; nt++) mma_f16(acc[mt][nt], ah, bh[nt]);
                if (NPROD == 2) {
                    uint32_t al[4];
                    ldsm4(al, addr + ATILE_B);
                    #pragma unroll
                    for (int nt = 0; nt < 8; nt++) mma_f16(acc[mt][nt], al, bh[nt]);
                }
            }
        }
    }

    // ---------------- epilogue straight from registers ----------------
    const int r_loc = m_warp + (lane >> 2);          // local row (of 128), +8 pair
    const int c_loc = n_warp + (lane & 3) * 2;       // local col (of 256)

    #pragma unroll
    for (int mt = 0; mt < 2; mt++) {
        #pragma unroll
        for (int half = 0; half < 2; half++) {
            int r = m0 + r_loc + mt * 16 + half * 8;
            #pragma unroll
            for (int nt = 0; nt < 8; nt++) {
                int cc = n0 + c_loc + nt * 8;
                float v0 = acc[mt][nt][half * 2 + 0];
                float v1 = acc[mt][nt][half * 2 + 1];

                if (MODE == 0) {
                    int mat = n0 >> 10;              // tile-uniform (256 | 1024)
                    int nl = cc & 1023;
                    float f0 = v0 + g_bcat[cc];
                    float f1 = v1 + g_bcat[cc + 1];
                    if (mat == 2) {
                        *(float2*)&g_V[(size_t)r * DOUT + nl] = make_float2(f0, f1);
                    } else {                         // Q or K: single fp16
                        __half2 p; p.x = __float2half(f0); p.y = __float2half(f1);
                        __half* dst = (mat == 0) ? g_Qh : g_Kh;
                        *(__half2*)&dst[(size_t)r * DOUT + nl] = p;
                    }
                } else if (MODE == 1) {
                    const float scale = 0.03125f;    // 1/sqrt(1024)
                    float f0 = v0 * scale, f1 = v1 * scale;
                    if (n0 + 255 > m0) {             // diagonal crosses tile
                        if (cc     > r) f0 = -INFINITY;
                        if (cc + 1 > r) f1 = -INFINITY;
                    }
                    *(float2*)&g_S[((size_t)b * SEQ + r) * SEQ + cc] = make_float2(f0, f1);
                } else {
                    *(float2*)&out[((size_t)b * SEQ + r) * DOUT + cc] = make_float2(v0, v1);
                }
            }
        }
    }
}

// ---------------------------------------------------------------------------
// Prep kernels
// ---------------------------------------------------------------------------
__global__ __launch_bounds__(256) void prep_x_kernel(const float* __restrict__ x)
{
    size_t i = (size_t)blockIdx.x * 1024 + threadIdx.x * 4;
    float4 v = *(const float4*)&x[i];
    __half h, l;
    split2h(v.x, h, l); g_xh[i + 0] = h; g_xl[i + 0] = l;
    split2h(v.y, h, l); g_xh[i + 1] = h; g_xl[i + 1] = l;
    split2h(v.z, h, l); g_xh[i + 2] = h; g_xl[i + 2] = l;
    split2h(v.w, h, l); g_xh[i + 3] = h; g_xl[i + 3] = l;
}

__global__ void prep_bias_kernel(const float* __restrict__ bq,
                                 const float* __restrict__ bk,
                                 const float* __restrict__ bv)
{
    int i = blockIdx.x * 256 + threadIdx.x;   // 0..3071
    g_bcat[i] = (i < 1024) ? bq[i] : (i < 2048) ? bk[i - 1024] : bv[i - 2048];
}

// W [k][n] -> Wt [z*1024 + n][k], fp16
__global__ void prep_wt_kernel(const float* __restrict__ Wq,
                               const float* __restrict__ Wk,
                               const float* __restrict__ Wv)
{
    __shared__ float tl[32][33];
    const int z = blockIdx.z;
    const float* W = (z == 0) ? Wq : (z == 1) ? Wk : Wv;
    int kk = blockIdx.y * 32, nn = blockIdx.x * 32;
    int tx = threadIdx.x, ty = threadIdx.y;
    #pragma unroll
    for (int i = 0; i < 4; i++)
        tl[ty + i * 8][tx] = W[(size_t)(kk + ty + i * 8) * DOUT + nn + tx];
    __syncthreads();
    #pragma unroll
    for (int i = 0; i < 4; i++) {
        float f = tl[tx][ty + i * 8];        // = W[kk+tx][nn+ty+i*8]
        size_t row = (size_t)z * 1024 + nn + ty + i * 8;
        g_Wth[row * DIN + kk + tx] = __float2half(f);
    }
}

// V [b][j][d] -> Vt [b][d][j], fp16
__global__ void vtrans_kernel()
{
    __shared__ float tl[32][33];
    const int bz = blockIdx.z;
    int jj = blockIdx.x * 32, dd = blockIdx.y * 32;
    int tx = threadIdx.x, ty = threadIdx.y;
    #pragma unroll
    for (int i = 0; i < 4; i++)
        tl[ty + i * 8][tx] = g_V[((size_t)bz * SEQ + jj + ty + i * 8) * DOUT + dd + tx];
    __syncthreads();
    #pragma unroll
    for (int i = 0; i < 4; i++) {
        float f = tl[tx][ty + i * 8];        // = V[jj+tx][dd+ty+i*8]
        size_t row = (size_t)bz * DOUT + dd + ty + i * 8;
        g_Vth[row * SEQ + jj + tx] = __float2half(f);
    }
}

// ---------------------------------------------------------------------------
// Softmax; writes single-fp16 P over the causally live region (j < row_end)
// ---------------------------------------------------------------------------
__device__ __forceinline__ float wr_max(float v) {
    #pragma unroll
    for (int o = 16; o > 0; o >>= 1) v = fmaxf(v, __shfl_xor_sync(0xFFFFFFFFu, v, o));
    return v;
}
__device__ __forceinline__ float wr_sum(float v) {
    #pragma unroll
    for (int o = 16; o > 0; o >>= 1) v += __shfl_xor_sync(0xFFFFFFFFu, v, o);
    return v;
}

__global__ __launch_bounds__(256) void softmax_kernel()
{
    const size_t row = blockIdx.x;          // b*SEQ + i
    const int i_in_b = (int)(row & (SEQ - 1));
    const int row_end = ((i_in_b >> 7) + 1) << 7;   // P region consumed by PV
    const float* Srow = g_S + row * SEQ;
    const int t = threadIdx.x;
    __shared__ float red[8];

    float vals[8];
    float mx = -INFINITY;
    #pragma unroll
    for (int l = 0; l < 8; l++) {
        int j = t + l * 256;
        vals[l] = (j < row_end) ? Srow[j] : -INFINITY;
        mx = fmaxf(mx, vals[l]);
    }
    mx = wr_max(mx);
    if ((t & 31) == 0) red[t >> 5] = mx;
    __syncthreads();
    if (t < 8) {
        float v = red[t];
        #pragma unroll
        for (int o = 4; o > 0; o >>= 1) v = fmaxf(v, __shfl_xor_sync(0xFFu, v, o));
        red[t] = v;
    }
    __syncthreads();
    mx = red[0];

    float sum = 0.f;
    #pragma unroll
    for (int l = 0; l < 8; l++) {
        float e = (vals[l] == -INFINITY) ? 0.f : __expf(vals[l] - mx);
        vals[l] = e;
        sum += e;
    }
    sum = wr_sum(sum);
    __syncthreads();
    if ((t & 31) == 0) red[t >> 5] = sum;
    __syncthreads();
    if (t < 8) {
        float v = red[t];
        #pragma unroll
        for (int o = 4; o > 0; o >>= 1) v += __shfl_xor_sync(0xFFu, v, o);
        red[t] = v;
    }
    __syncthreads();
    const float inv = 1.f / red[0];

    #pragma unroll
    for (int l = 0; l < 8; l++) {
        int j = t + l * 256;
        if (j < row_end)
            g_Ph[row * SEQ + j] = __float2half(vals[l] * inv);
    }
}

// ---------------------------------------------------------------------------
extern "C" void kernel_launch(void* const* d_in, const int* in_sizes, int n_in,
                              void* d_out, int out_size)
{
    const float* x  = (const float*)d_in[0];
    const float* Wq = (const float*)d_in[1];
    const float* bq = (const float*)d_in[2];
    const float* Wk = (const float*)d_in[3];
    const float* bk = (const float*)d_in[4];
    const float* Wv = (const float*)d_in[5];
    const float* bv = (const float*)d_in[6];
    float* out = (float*)d_out;

    const int SM0  = NSTAGE * (2 * ATILE_B + BTILE_B);   // 221184
    const int SM12 = NSTAGE * (ATILE_B + BTILE_B);       // 165888

    cudaFuncSetAttribute(gemm_kernel<0>, cudaFuncAttributeMaxDynamicSharedMemorySize, SM0);
    cudaFuncSetAttribute(gemm_kernel<1>, cudaFuncAttributeMaxDynamicSharedMemorySize, SM12);
    cudaFuncSetAttribute(gemm_kernel<2>, cudaFuncAttributeMaxDynamicSharedMemorySize, SM12);

    prep_x_kernel<<<MTOT * DIN / 1024, 256>>>(x);
    prep_bias_kernel<<<NCAT / 256, 256>>>(bq, bk, bv);
    prep_wt_kernel<<<dim3(DOUT / 32, DIN / 32, 3), dim3(32, 8)>>>(Wq, Wk, Wv);

    // QKV: N = 3072 concat (12 tiles of 256), M = 8192 (64 tiles of 128)
    gemm_kernel<0><<<dim3(NCAT / 256, MTOT / 128), NTHREADS, SM0>>>(out);

    vtrans_kernel<<<dim3(SEQ / 32, DOUT / 32, BATCH), dim3(32, 8)>>>();

    // Scores: 128x256 causal tiles; 72 per batch (single product)
    gemm_kernel<1><<<dim3(72, BATCH), NTHREADS, SM12>>>(out);

    softmax_kernel<<<BATCH * SEQ, 256>>>();

    // PV: K truncated by causality; N = 1024 (4 tiles of 256), single product
    gemm_kernel<2><<<dim3(DOUT / 256, SEQ / 128, BATCH), NTHREADS, SM12>>>(out);
}

// round 17
// speedup vs baseline: 2.3418x; 1.3308x over previous
#include <cuda_runtime.h>
#include <cuda_fp16.h>
#include <math.h>
#include <stdint.h>

#define BATCH 4
#define SEQ   2048
#define DIN   1024
#define DOUT  1024
#define MTOT  (BATCH*SEQ)            // 8192
#define NCAT  (3*DOUT)               // 3072

// ---------------------------------------------------------------------------
// Scratch — everything fp16 single precision operands, fp32 accum/S.
// ---------------------------------------------------------------------------
__device__ __half g_xh[(size_t)MTOT*DIN];
__device__ __half g_Wth[(size_t)NCAT*DIN];          // W^T concat [n][k]
__device__ float  g_bcat[NCAT];
__device__ __half g_Qh[(size_t)MTOT*DOUT];
__device__ __half g_Kh[(size_t)MTOT*DOUT];
__device__ __half g_Vth[(size_t)BATCH*DOUT*SEQ];    // V^T [b][d][j]
__device__ float  g_S [(size_t)BATCH*SEQ*SEQ];
__device__ __half g_Ph[(size_t)BATCH*SEQ*SEQ];

// ---------------------------------------------------------------------------
// Baseline-PTX tensor helpers (mma.sync + ldmatrix + cp.async; plain sm_103)
// ---------------------------------------------------------------------------
__device__ __forceinline__ uint32_t smem_u32(const void* p) {
    uint32_t a;
    asm("{ .reg .u64 t; cvta.to.shared.u64 t, %1; cvt.u32.u64 %0, t; }" : "=r"(a) : "l"(p));
    return a;
}
__device__ __forceinline__ void ldsm4(uint32_t* r, uint32_t a) {
    asm volatile("ldmatrix.sync.aligned.m8n8.x4.shared.b16 {%0,%1,%2,%3}, [%4];"
        : "=r"(r[0]), "=r"(r[1]), "=r"(r[2]), "=r"(r[3]) : "r"(a));
}
__device__ __forceinline__ void mma_f16(float* c, const uint32_t* a, const uint32_t* b) {
    asm volatile("mma.sync.aligned.m16n8k16.row.col.f32.f16.f16.f32 "
        "{%0,%1,%2,%3}, {%4,%5,%6,%7}, {%8,%9}, {%0,%1,%2,%3};"
        : "+f"(c[0]), "+f"(c[1]), "+f"(c[2]), "+f"(c[3])
        : "r"(a[0]), "r"(a[1]), "r"(a[2]), "r"(a[3]), "r"(b[0]), "r"(b[1]));
}
__device__ __forceinline__ void cp16(uint32_t saddr, const void* g) {
    asm volatile("cp.async.cg.shared.global [%0], [%1], 16;" :: "r"(saddr), "l"(g));
}
#define CP_COMMIT() asm volatile("cp.async.commit_group;" ::: "memory")
#define CP_WAIT(n)  asm volatile("cp.async.wait_group %0;" :: "n"(n) : "memory")

// ---------------------------------------------------------------------------
// CTA tile: 128 (M) x 256 (N), K-chunk 64, row stride 144 B.
// Stage: A(128x64) + B(256x64) = 18432 + 36864 = 55296 B; 3-stage = 165888 B.
// ---------------------------------------------------------------------------
#define TSTRIDE_B 144
#define ATILE_B   18432
#define BTILE_B   36864
#define STAGE_B   (ATILE_B + BTILE_B)
#define NSTAGE    3
#define SMEM_SZ   (NSTAGE*STAGE_B)
#define NTHREADS  512

// MODE 0: QKV  (A=x, B=Wt, N over 3072; V tiles write V^T fp16 directly)
// MODE 1: scores (A=Q, B=K, causal tiles only)
// MODE 2: PV   (A=P, B=Vt, K truncated)
template<int MODE>
__global__ __launch_bounds__(NTHREADS) void gemm_kernel(float* __restrict__ out)
{
    extern __shared__ char smem[];
    const uint32_t sb = smem_u32(smem);
    const int t = threadIdx.x;
    const int wid = t >> 5, lane = t & 31;
    // 16 warps: 4 m-groups x 4 n-groups; each warp owns a 32x64 subtile.
    const int m_warp = (wid & 3) * 32;
    const int n_warp = (wid >> 2) * 64;

    const __half *Ah, *Bh;
    size_t sA, sB;
    int m0, n0, nchunks, b = 0;

    if (MODE == 0) {
        m0 = blockIdx.y * 128; n0 = blockIdx.x * 256;
        Ah = g_xh + (size_t)m0 * DIN;
        Bh = g_Wth + (size_t)n0 * DIN;
        sA = DIN; sB = DIN; nchunks = DIN / 64;
    } else if (MODE == 1) {
        b = blockIdx.y;
        // causal tiles, 128x256: row it has (it/2)+1 tiles; 72 per batch
        int x = blockIdx.x, it = 0, acc0 = 0;
        while (acc0 + (it / 2 + 1) <= x) { acc0 += it / 2 + 1; it++; }
        int jt = x - acc0;
        m0 = it * 128; n0 = jt * 256;
        Ah = g_Qh + ((size_t)b * SEQ + m0) * DOUT;
        Bh = g_Kh + ((size_t)b * SEQ + n0) * DOUT;
        sA = DOUT; sB = DOUT; nchunks = DOUT / 64;
    } else {
        b = blockIdx.z;
        m0 = blockIdx.y * 128; n0 = blockIdx.x * 256;
        Ah = g_Ph + ((size_t)b * SEQ + m0) * SEQ;
        Bh = g_Vth + ((size_t)b * DOUT + n0) * SEQ;
        sA = SEQ; sB = SEQ; nchunks = (blockIdx.y + 1) * 2;   // >= 2 always
    }

    float acc[2][8][4] = {};   // [mt][nt][frag], 64 regs

    // async chunk loader: A (128x8) + B (256x8) 16B-chunks = 6 cp16/thread
    auto issue_chunk = [&](int buf, int kc) {
        const int k0 = kc * 64;
        const uint32_t sbase = sb + buf * STAGE_B;
        #pragma unroll
        for (int l = 0; l < 2; l++) {            // A tile: 128 rows
            int e  = l * 512 + t;                // 0..1023
            int r  = e >> 3;
            int c8 = e & 7;
            cp16(sbase + (uint32_t)(r * TSTRIDE_B + c8 * 16),
                 Ah + (size_t)r * sA + k0 + c8 * 8);
        }
        #pragma unroll
        for (int l = 0; l < 4; l++) {            // B tile: 256 rows
            int e  = l * 512 + t;                // 0..2047
            int r  = e >> 3;
            int c8 = e & 7;
            cp16(sbase + ATILE_B + (uint32_t)(r * TSTRIDE_B + c8 * 16),
                 Bh + (size_t)r * sB + k0 + c8 * 8);
        }
        CP_COMMIT();
    };

    // prologue: prefetch up to NSTAGE-1 = 2 chunks
    const int npro = (nchunks < NSTAGE - 1) ? nchunks : (NSTAGE - 1);
    for (int kc = 0; kc < npro; kc++) issue_chunk(kc, kc);

    for (int c = 0; c < nchunks; c++) {
        if (c + 1 < nchunks) { CP_WAIT(1); } else { CP_WAIT(0); }
        __syncthreads();                     // chunk c resident; stage (c-1)%3 free
        if (c + NSTAGE - 1 < nchunks)
            issue_chunk((c + NSTAGE - 1) % NSTAGE, c + NSTAGE - 1);

        const uint32_t base = sb + (c % NSTAGE) * STAGE_B;
        const int arow = m_warp + (lane & 7) + ((lane >> 3) & 1) * 8;
        const uint32_t acol = (lane >> 4) * 16;
        // B ldsm4 over an nt-pair (16 n-rows x 16 k)
        const int brow4 = n_warp + (lane & 7) + (lane >> 4) * 8;
        const uint32_t bcol4 = ((lane >> 3) & 1) * 16;

        #pragma unroll
        for (int ks = 0; ks < 4; ks++) {
            const uint32_t kb = ks * 32;     // 16 fp16 = 32 bytes
            uint32_t bh[8][2];
            #pragma unroll
            for (int q = 0; q < 4; q++) {
                uint32_t addr = base + ATILE_B + (uint32_t)(brow4 + q * 16) * TSTRIDE_B + bcol4 + kb;
                uint32_t r4[4];
                ldsm4(r4, addr);
                bh[2*q][0] = r4[0]; bh[2*q][1] = r4[1];
                bh[2*q+1][0] = r4[2]; bh[2*q+1][1] = r4[3];
            }
            #pragma unroll
            for (int mt = 0; mt < 2; mt++) {
                uint32_t addr = base + (uint32_t)(arow + mt * 16) * TSTRIDE_B + acol + kb;
                uint32_t ah[4];
                ldsm4(ah, addr);
                #pragma unroll
                for (int nt = 0; nt < 8; nt++) mma_f16(acc[mt][nt], ah, bh[nt]);
            }
        }
    }

    // ---------------- epilogue straight from registers ----------------
    const int r_loc = m_warp + (lane >> 2);          // local row (of 128), +8 pair
    const int c_loc = n_warp + (lane & 3) * 2;       // local col (of 256)

    #pragma unroll
    for (int mt = 0; mt < 2; mt++) {
        #pragma unroll
        for (int half = 0; half < 2; half++) {
            int r = m0 + r_loc + mt * 16 + half * 8;
            #pragma unroll
            for (int nt = 0; nt < 8; nt++) {
                int cc = n0 + c_loc + nt * 8;
                float v0 = acc[mt][nt][half * 2 + 0];
                float v1 = acc[mt][nt][half * 2 + 1];

                if (MODE == 0) {
                    int mat = n0 >> 10;              // tile-uniform (256 | 1024)
                    int nl = cc & 1023;
                    float f0 = v0 + g_bcat[cc];
                    float f1 = v1 + g_bcat[cc + 1];
                    if (mat == 2) {
                        // V: write V^T [b][d][j] fp16 directly (fused vtrans)
                        int bb = r >> 11;
                        int j  = r & (SEQ - 1);
                        g_Vth[((size_t)bb * DOUT + nl)     * SEQ + j] = __float2half(f0);
                        g_Vth[((size_t)bb * DOUT + nl + 1) * SEQ + j] = __float2half(f1);
                    } else {                         // Q or K: fp16 row-major
                        __half2 p; p.x = __float2half(f0); p.y = __float2half(f1);
                        __half* dst = (mat == 0) ? g_Qh : g_Kh;
                        *(__half2*)&dst[(size_t)r * DOUT + nl] = p;
                    }
                } else if (MODE == 1) {
                    const float scale = 0.03125f;    // 1/sqrt(1024)
                    float f0 = v0 * scale, f1 = v1 * scale;
                    if (n0 + 255 > m0) {             // diagonal crosses tile
                        if (cc     > r) f0 = -INFINITY;
                        if (cc + 1 > r) f1 = -INFINITY;
                    }
                    *(float2*)&g_S[((size_t)b * SEQ + r) * SEQ + cc] = make_float2(f0, f1);
                } else {
                    *(float2*)&out[((size_t)b * SEQ + r) * DOUT + cc] = make_float2(v0, v1);
                }
            }
        }
    }
}

// ---------------------------------------------------------------------------
// Prep kernels
// ---------------------------------------------------------------------------
__global__ __launch_bounds__(256) void prep_x_kernel(const float* __restrict__ x)
{
    size_t i = (size_t)blockIdx.x * 1024 + threadIdx.x * 4;
    float4 v = *(const float4*)&x[i];
    __half2 a; a.x = __float2half(v.x); a.y = __float2half(v.y);
    __half2 c; c.x = __float2half(v.z); c.y = __float2half(v.w);
    *(__half2*)&g_xh[i + 0] = a;
    *(__half2*)&g_xh[i + 2] = c;
}

__global__ void prep_bias_kernel(const float* __restrict__ bq,
                                 const float* __restrict__ bk,
                                 const float* __restrict__ bv)
{
    int i = blockIdx.x * 256 + threadIdx.x;   // 0..3071
    g_bcat[i] = (i < 1024) ? bq[i] : (i < 2048) ? bk[i - 1024] : bv[i - 2048];
}

// W [k][n] -> Wt [z*1024 + n][k], fp16
__global__ void prep_wt_kernel(const float* __restrict__ Wq,
                               const float* __restrict__ Wk,
                               const float* __restrict__ Wv)
{
    __shared__ float tl[32][33];
    const int z = blockIdx.z;
    const float* W = (z == 0) ? Wq : (z == 1) ? Wk : Wv;
    int kk = blockIdx.y * 32, nn = blockIdx.x * 32;
    int tx = threadIdx.x, ty = threadIdx.y;
    #pragma unroll
    for (int i = 0; i < 4; i++)
        tl[ty + i * 8][tx] = W[(size_t)(kk + ty + i * 8) * DOUT + nn + tx];
    __syncthreads();
    #pragma unroll
    for (int i = 0; i < 4; i++) {
        float f = tl[tx][ty + i * 8];        // = W[kk+tx][nn+ty+i*8]
        size_t row = (size_t)z * 1024 + nn + ty + i * 8;
        g_Wth[row * DIN + kk + tx] = __float2half(f);
    }
}

// ---------------------------------------------------------------------------
// Softmax; writes fp16 P over the causally live region (j < row_end)
// ---------------------------------------------------------------------------
__device__ __forceinline__ float wr_max(float v) {
    #pragma unroll
    for (int o = 16; o > 0; o >>= 1) v = fmaxf(v, __shfl_xor_sync(0xFFFFFFFFu, v, o));
    return v;
}
__device__ __forceinline__ float wr_sum(float v) {
    #pragma unroll
    for (int o = 16; o > 0; o >>= 1) v += __shfl_xor_sync(0xFFFFFFFFu, v, o);
    return v;
}

__global__ __launch_bounds__(256) void softmax_kernel()
{
    const size_t row = blockIdx.x;          // b*SEQ + i
    const int i_in_b = (int)(row & (SEQ - 1));
    const int row_end = ((i_in_b >> 7) + 1) << 7;   // P region consumed by PV
    const float* Srow = g_S + row * SEQ;
    const int t = threadIdx.x;
    __shared__ float red[8];

    float vals[8];
    float mx = -INFINITY;
    #pragma unroll
    for (int l = 0; l < 8; l++) {
        int j = t + l * 256;
        vals[l] = (j < row_end) ? Srow[j] : -INFINITY;
        mx = fmaxf(mx, vals[l]);
    }
    mx = wr_max(mx);
    if ((t & 31) == 0) red[t >> 5] = mx;
    __syncthreads();
    if (t < 8) {
        float v = red[t];
        #pragma unroll
        for (int o = 4; o > 0; o >>= 1) v = fmaxf(v, __shfl_xor_sync(0xFFu, v, o));
        red[t] = v;
    }
    __syncthreads();
    mx = red[0];

    float sum = 0.f;
    #pragma unroll
    for (int l = 0; l < 8; l++) {
        float e = (vals[l] == -INFINITY) ? 0.f : __expf(vals[l] - mx);
        vals[l] = e;
        sum += e;
    }
    sum = wr_sum(sum);
    __syncthreads();
    if ((t & 31) == 0) red[t >> 5] = sum;
    __syncthreads();
    if (t < 8) {
        float v = red[t];
        #pragma unroll
        for (int o = 4; o > 0; o >>= 1) v += __shfl_xor_sync(0xFFu, v, o);
        red[t] = v;
    }
    __syncthreads();
    const float inv = 1.f / red[0];

    #pragma unroll
    for (int l = 0; l < 8; l++) {
        int j = t + l * 256;
        if (j < row_end)
            g_Ph[row * SEQ + j] = __float2half(vals[l] * inv);
    }
}

// ---------------------------------------------------------------------------
extern "C" void kernel_launch(void* const* d_in, const int* in_sizes, int n_in,
                              void* d_out, int out_size)
{
    const float* x  = (const float*)d_in[0];
    const float* Wq = (const float*)d_in[1];
    const float* bq = (const float*)d_in[2];
    const float* Wk = (const float*)d_in[3];
    const float* bk = (const float*)d_in[4];
    const float* Wv = (const float*)d_in[5];
    const float* bv = (const float*)d_in[6];
    float* out = (float*)d_out;

    cudaFuncSetAttribute(gemm_kernel<0>, cudaFuncAttributeMaxDynamicSharedMemorySize, SMEM_SZ);
    cudaFuncSetAttribute(gemm_kernel<1>, cudaFuncAttributeMaxDynamicSharedMemorySize, SMEM_SZ);
    cudaFuncSetAttribute(gemm_kernel<2>, cudaFuncAttributeMaxDynamicSharedMemorySize, SMEM_SZ);

    prep_x_kernel<<<MTOT * DIN / 1024, 256>>>(x);
    prep_bias_kernel<<<NCAT / 256, 256>>>(bq, bk, bv);
    prep_wt_kernel<<<dim3(DOUT / 32, DIN / 32, 3), dim3(32, 8)>>>(Wq, Wk, Wv);

    // QKV: N = 3072 concat (12 tiles of 256), M = 8192 (64 tiles of 128)
    // V-column tiles write V^T fp16 directly (vtrans fused).
    gemm_kernel<0><<<dim3(NCAT / 256, MTOT / 128), NTHREADS, SMEM_SZ>>>(out);

    // Scores: 128x256 causal tiles; 72 per batch
    gemm_kernel<1><<<dim3(72, BATCH), NTHREADS, SMEM_SZ>>>(out);

    softmax_kernel<<<BATCH * SEQ, 256>>>();

    // PV: K truncated by causality; N = 1024 (4 tiles of 256)
    gemm_kernel<2><<<dim3(DOUT / 256, SEQ / 128, BATCH), NTHREADS, SMEM_SZ>>>(out);
}